// round 15
// baseline (speedup 1.0000x reference)
#include <cuda_runtime.h>
#include <cstdint>

// sbvr decode:
//   out[g*16 + l] = sum_s coeff_cache[coeff_idx[g]][s] * ((bvr[g][s] >> l) & 1)
// G = 4,194,304 groups, S = 4, L = 16.
//
// R13 -> R14: attack the dominant L1 cost, the coeff gather's within-LDG
// replays (8 lines @2.07cyc = 16.6 of ~26 L1-cyc/warp-iter). Replace the one
// divergent LDG.128 with EIGHT uniform-address LDG.128s (one per quad's row):
// every lane loads all 8 rows -> each LDG touches exactly ONE line = 1.0cyc
// wavefront + broadcast return. Lane then selects its quad's row via a
// 28-selp binary tree on thread-constant qid bits (ALU pipe - idle capacity).
// Distinct destination registers -> no R12-style WAW serialization.
// Uniform addresses come from a 2KB smem stage of the block's idx tile
// (loaded once, read back via 2 uniform broadcast LDS.128/iter).
// Skeleton otherwise = R6 (best): block-contiguous immediate offsets, ITER=8,
// bvr dist 1, gather dist 1, pipe-balanced asm decode, __stcs stores.

static constexpr unsigned QT_TOTAL = 16u * 1024u * 1024u;  // 4M groups * 4 quarters
static constexpr int      BLOCK    = 256;
static constexpr int      ITER     = 8;                    // quarter-groups per thread
static constexpr unsigned BLOCKS   = QT_TOTAL / (BLOCK * ITER);  // 8192
static constexpr int      GSTRIDE  = BLOCK / 4;            // 64 groups per iteration
static constexpr int      GPB      = BLOCK * ITER / 4;     // 512 groups per block

// Pipe-balanced decode: lop3 with predicate output (ALU; AND+test in one op)
// feeding predicated add.f32 (FMA pipe). Exact fp32 -> rel_err 0.
__device__ __forceinline__ float4 decode_quarter(int4 w, float4 c, unsigned m0)
{
    float4 r;
    asm(
    "{\n\t"
    ".reg .pred q, p0, p1, p2, p3;\n\t"
    ".reg .b32  t, m1, m2, m3;\n\t"
    "setp.ne.u32 q, %4, %4;\n\t"
    "shl.b32 m1, %8, 1;\n\t"
    "shl.b32 m2, %8, 2;\n\t"
    "shl.b32 m3, %8, 3;\n\t"
    "lop3.or.b32 t|p0, %4, %8, %4, 0xC0, q;\n\t"
    "lop3.or.b32 t|p1, %5, %8, %5, 0xC0, q;\n\t"
    "lop3.or.b32 t|p2, %6, %8, %6, 0xC0, q;\n\t"
    "lop3.or.b32 t|p3, %7, %8, %7, 0xC0, q;\n\t"
    "selp.f32 %0, %9, 0f00000000, p0;\n\t"
    "@p1 add.rn.f32 %0, %0, %10;\n\t"
    "@p2 add.rn.f32 %0, %0, %11;\n\t"
    "@p3 add.rn.f32 %0, %0, %12;\n\t"
    "lop3.or.b32 t|p0, %4, m1, %4, 0xC0, q;\n\t"
    "lop3.or.b32 t|p1, %5, m1, %5, 0xC0, q;\n\t"
    "lop3.or.b32 t|p2, %6, m1, %6, 0xC0, q;\n\t"
    "lop3.or.b32 t|p3, %7, m1, %7, 0xC0, q;\n\t"
    "selp.f32 %1, %9, 0f00000000, p0;\n\t"
    "@p1 add.rn.f32 %1, %1, %10;\n\t"
    "@p2 add.rn.f32 %1, %1, %11;\n\t"
    "@p3 add.rn.f32 %1, %1, %12;\n\t"
    "lop3.or.b32 t|p0, %4, m2, %4, 0xC0, q;\n\t"
    "lop3.or.b32 t|p1, %5, m2, %5, 0xC0, q;\n\t"
    "lop3.or.b32 t|p2, %6, m2, %6, 0xC0, q;\n\t"
    "lop3.or.b32 t|p3, %7, m2, %7, 0xC0, q;\n\t"
    "selp.f32 %2, %9, 0f00000000, p0;\n\t"
    "@p1 add.rn.f32 %2, %2, %10;\n\t"
    "@p2 add.rn.f32 %2, %2, %11;\n\t"
    "@p3 add.rn.f32 %2, %2, %12;\n\t"
    "lop3.or.b32 t|p0, %4, m3, %4, 0xC0, q;\n\t"
    "lop3.or.b32 t|p1, %5, m3, %5, 0xC0, q;\n\t"
    "lop3.or.b32 t|p2, %6, m3, %6, 0xC0, q;\n\t"
    "lop3.or.b32 t|p3, %7, m3, %7, 0xC0, q;\n\t"
    "selp.f32 %3, %9, 0f00000000, p0;\n\t"
    "@p1 add.rn.f32 %3, %3, %10;\n\t"
    "@p2 add.rn.f32 %3, %3, %11;\n\t"
    "@p3 add.rn.f32 %3, %3, %12;\n\t"
    "}\n\t"
    : "=f"(r.x), "=f"(r.y), "=f"(r.z), "=f"(r.w)
    : "r"(w.x), "r"(w.y), "r"(w.z), "r"(w.w),
      "r"(m0),
      "f"(c.x), "f"(c.y), "f"(c.z), "f"(c.w));
    return r;
}

// Binary select tree: pick this lane's quad row from the 8 broadcast rows.
// b0/b1/b2 are thread-constant (qid bits) -> pure selp chains, no divergence.
__device__ __forceinline__ float4 sel8(const float4* cu, bool b0, bool b1, bool b2)
{
    float4 s01, s23, s45, s67, t03, t47, r;
    s01.x = b0 ? cu[1].x : cu[0].x;  s01.y = b0 ? cu[1].y : cu[0].y;
    s01.z = b0 ? cu[1].z : cu[0].z;  s01.w = b0 ? cu[1].w : cu[0].w;
    s23.x = b0 ? cu[3].x : cu[2].x;  s23.y = b0 ? cu[3].y : cu[2].y;
    s23.z = b0 ? cu[3].z : cu[2].z;  s23.w = b0 ? cu[3].w : cu[2].w;
    s45.x = b0 ? cu[5].x : cu[4].x;  s45.y = b0 ? cu[5].y : cu[4].y;
    s45.z = b0 ? cu[5].z : cu[4].z;  s45.w = b0 ? cu[5].w : cu[4].w;
    s67.x = b0 ? cu[7].x : cu[6].x;  s67.y = b0 ? cu[7].y : cu[6].y;
    s67.z = b0 ? cu[7].z : cu[6].z;  s67.w = b0 ? cu[7].w : cu[6].w;
    t03.x = b1 ? s23.x : s01.x;  t03.y = b1 ? s23.y : s01.y;
    t03.z = b1 ? s23.z : s01.z;  t03.w = b1 ? s23.w : s01.w;
    t47.x = b1 ? s67.x : s45.x;  t47.y = b1 ? s67.y : s45.y;
    t47.z = b1 ? s67.z : s45.z;  t47.w = b1 ? s67.w : s45.w;
    r.x = b2 ? t47.x : t03.x;  r.y = b2 ? t47.y : t03.y;
    r.z = b2 ? t47.z : t03.z;  r.w = b2 ? t47.w : t03.w;
    return r;
}

__global__ __launch_bounds__(BLOCK, 4) void sbvr_kernel(
    const float4* __restrict__ coeff_cache,   // [65536] rows of 4 floats
    const int*    __restrict__ coeff_idx,     // [G]
    const int4*   __restrict__ bvr,           // [G]
    float4*       __restrict__ out)           // [4*G]
{
    __shared__ int sidx[GPB];                 // 2KB: block's idx tile

    unsigned tid = threadIdx.x;
    unsigned t   = blockIdx.x * (unsigned)(BLOCK * ITER) + tid;

    // Stage the block's 512 coeff indices into smem (coalesced, once).
    {
        const int2* src = (const int2*)(coeff_idx + blockIdx.x * (unsigned)GPB);
        ((int2*)sidx)[tid] = __ldcs(src + tid);
    }
    __syncthreads();

    const int4* wp = bvr + (t >> 2);
    float4*     op = out + t;

    unsigned m0  = 1u << ((t & 3u) * 4u);     // invariant over i
    unsigned qid = (tid >> 2) & 7u;           // quad id within warp
    bool b0 = qid & 1u, b1 = qid & 2u, b2 = qid & 4u;
    unsigned wbase = (tid >> 5) * 8u;         // warp's group offset within iter slab

    // Rolling state: cur[8] = the 8 broadcast rows for the CURRENT iteration.
    float4 cur[8];
    int4   wv[2];                             // bvr, distance 1

    // Prologue: issue iteration 0's gathers + bvr.
    #pragma unroll
    for (int k = 0; k < 8; k++)
        cur[k] = __ldcg(coeff_cache + (unsigned)sidx[wbase + k]);
    wv[0] = __ldcs(wp);

    #pragma unroll
    for (int i = 0; i < ITER; i++) {
        if (i + 1 < ITER)                     // bvr for iter i+1
            wv[(i + 1) & 1] = __ldcs(wp + (i + 1) * GSTRIDE);

        // Select this lane's row for iter i (consumes cur; cur regs then reused).
        float4 c = sel8(cur, b0, b1, b2);

        if (i + 1 < ITER) {                   // issue iter i+1's 8 uniform gathers
            unsigned sb = (unsigned)(i + 1) * GSTRIDE + wbase;
            #pragma unroll
            for (int k = 0; k < 8; k++)
                cur[k] = __ldcg(coeff_cache + (unsigned)sidx[sb + k]);
        }

        float4 r = decode_quarter(wv[i & 1], c, m0);
        __stcs(op + i * BLOCK, r);
    }
}

extern "C" void kernel_launch(void* const* d_in, const int* in_sizes, int n_in,
                              void* d_out, int out_size)
{
    const float4* coeff_cache = (const float4*)d_in[0];  // [65536,4] f32
    const int*    coeff_idx   = (const int*)d_in[1];     // [G] i32
    const int4*   bvr         = (const int4*)d_in[2];    // [G,4] i32
    float4*       out         = (float4*)d_out;          // [8192,8192] f32

    (void)in_sizes; (void)n_in; (void)out_size;

    sbvr_kernel<<<BLOCKS, BLOCK>>>(coeff_cache, coeff_idx, bvr, out);
}

// round 16
// speedup vs baseline: 1.6259x; 1.6259x over previous
#include <cuda_runtime.h>
#include <cstdint>

// sbvr decode:
//   out[g*16 + l] = sum_s coeff_cache[coeff_idx[g]][s] * ((bvr[g][s] >> l) & 1)
// G = 4,194,304 groups, S = 4, L = 16.
//
// R15 -> R16: revert broadcast-gather (return-path wavefronts quadrupled ->
// 100us; L1 cost = max(lines, bytes/128) and the divergent LDG.128 gather is
// already AT its 512B-return floor). Back to the R6 optimum shape with ONE
// isolated change: coeff gather prefetch distance 1 -> 2 (idx distance 4,
// bvr distance 2) to close the ~150cyc of exposed L2 latency per iteration.
// Everything else identical to the 61.9us best: block-contiguous immediate
// offsets, ITER=8, pipe-balanced asm decode, __ldcs/__ldcg/__stcs, (256,6).

static constexpr unsigned QT_TOTAL = 16u * 1024u * 1024u;  // 4M groups * 4 quarters
static constexpr int      BLOCK    = 256;
static constexpr int      ITER     = 8;                    // quarter-groups per thread
static constexpr int      PF_I     = 4;                    // idx prefetch distance
static constexpr int      PF_W     = 2;                    // bvr prefetch distance
static constexpr int      PF_C     = 2;                    // gather prefetch distance
static constexpr unsigned BLOCKS   = QT_TOTAL / (BLOCK * ITER);  // 8192
static constexpr int      GSTRIDE  = BLOCK / 4;            // 64 groups per iteration

// Pipe-balanced decode: lop3 with predicate output (ALU; AND+test in one op)
// feeding predicated add.f32 (FMA pipe). Exact fp32 -> rel_err 0.
__device__ __forceinline__ float4 decode_quarter(int4 w, float4 c, unsigned m0)
{
    float4 r;
    asm(
    "{\n\t"
    ".reg .pred q, p0, p1, p2, p3;\n\t"
    ".reg .b32  t, m1, m2, m3;\n\t"
    "setp.ne.u32 q, %4, %4;\n\t"
    "shl.b32 m1, %8, 1;\n\t"
    "shl.b32 m2, %8, 2;\n\t"
    "shl.b32 m3, %8, 3;\n\t"
    // ---- element 0 ----
    "lop3.or.b32 t|p0, %4, %8, %4, 0xC0, q;\n\t"
    "lop3.or.b32 t|p1, %5, %8, %5, 0xC0, q;\n\t"
    "lop3.or.b32 t|p2, %6, %8, %6, 0xC0, q;\n\t"
    "lop3.or.b32 t|p3, %7, %8, %7, 0xC0, q;\n\t"
    "selp.f32 %0, %9, 0f00000000, p0;\n\t"
    "@p1 add.rn.f32 %0, %0, %10;\n\t"
    "@p2 add.rn.f32 %0, %0, %11;\n\t"
    "@p3 add.rn.f32 %0, %0, %12;\n\t"
    // ---- element 1 ----
    "lop3.or.b32 t|p0, %4, m1, %4, 0xC0, q;\n\t"
    "lop3.or.b32 t|p1, %5, m1, %5, 0xC0, q;\n\t"
    "lop3.or.b32 t|p2, %6, m1, %6, 0xC0, q;\n\t"
    "lop3.or.b32 t|p3, %7, m1, %7, 0xC0, q;\n\t"
    "selp.f32 %1, %9, 0f00000000, p0;\n\t"
    "@p1 add.rn.f32 %1, %1, %10;\n\t"
    "@p2 add.rn.f32 %1, %1, %11;\n\t"
    "@p3 add.rn.f32 %1, %1, %12;\n\t"
    // ---- element 2 ----
    "lop3.or.b32 t|p0, %4, m2, %4, 0xC0, q;\n\t"
    "lop3.or.b32 t|p1, %5, m2, %5, 0xC0, q;\n\t"
    "lop3.or.b32 t|p2, %6, m2, %6, 0xC0, q;\n\t"
    "lop3.or.b32 t|p3, %7, m2, %7, 0xC0, q;\n\t"
    "selp.f32 %2, %9, 0f00000000, p0;\n\t"
    "@p1 add.rn.f32 %2, %2, %10;\n\t"
    "@p2 add.rn.f32 %2, %2, %11;\n\t"
    "@p3 add.rn.f32 %2, %2, %12;\n\t"
    // ---- element 3 ----
    "lop3.or.b32 t|p0, %4, m3, %4, 0xC0, q;\n\t"
    "lop3.or.b32 t|p1, %5, m3, %5, 0xC0, q;\n\t"
    "lop3.or.b32 t|p2, %6, m3, %6, 0xC0, q;\n\t"
    "lop3.or.b32 t|p3, %7, m3, %7, 0xC0, q;\n\t"
    "selp.f32 %3, %9, 0f00000000, p0;\n\t"
    "@p1 add.rn.f32 %3, %3, %10;\n\t"
    "@p2 add.rn.f32 %3, %3, %11;\n\t"
    "@p3 add.rn.f32 %3, %3, %12;\n\t"
    "}\n\t"
    : "=f"(r.x), "=f"(r.y), "=f"(r.z), "=f"(r.w)
    : "r"(w.x), "r"(w.y), "r"(w.z), "r"(w.w),
      "r"(m0),
      "f"(c.x), "f"(c.y), "f"(c.z), "f"(c.w));
    return r;
}

__global__ __launch_bounds__(BLOCK, 6) void sbvr_kernel(
    const float4* __restrict__ coeff_cache,   // [65536] rows of 4 floats
    const int*    __restrict__ coeff_idx,     // [G]
    const int4*   __restrict__ bvr,           // [G]
    float4*       __restrict__ out)           // [4*G]
{
    // Block-contiguous tile: quarter-indices [b*BLOCK*ITER, ...), iteration i
    // at +i*BLOCK. All per-iteration offsets are small immediates.
    unsigned t = blockIdx.x * (unsigned)(BLOCK * ITER) + threadIdx.x;
    unsigned g = t >> 2;

    const int*  ip = coeff_idx + g;
    const int4* wp = bvr + g;
    float4*     op = out + t;

    unsigned m0 = 1u << ((t & 3u) * 4u);   // BLOCK % 4 == 0: invariant over i

    int    ci[ITER];
    int4   w [ITER];
    float4 c [ITER];

    // Prologue: fill the three streams to their distances.
    #pragma unroll
    for (int i = 0; i < PF_I; i++)
        ci[i] = __ldcs(ip + i * GSTRIDE);
    #pragma unroll
    for (int i = 0; i < PF_W; i++)
        w[i] = __ldcs(wp + i * GSTRIDE);
    #pragma unroll
    for (int i = 0; i < PF_C; i++)
        c[i] = __ldcg(coeff_cache + ci[i]);

    #pragma unroll
    for (int i = 0; i < ITER; i++) {
        if (i + PF_I < ITER)                      // idx for iter i+4
            ci[i + PF_I] = __ldcs(ip + (i + PF_I) * GSTRIDE);
        if (i + PF_W < ITER)                      // bvr for iter i+2
            w[i + PF_W] = __ldcs(wp + (i + PF_W) * GSTRIDE);
        if (i + PF_C < ITER)                      // gather for iter i+2
            c[i + PF_C] = __ldcg(coeff_cache + ci[i + PF_C]);

        float4 r = decode_quarter(w[i], c[i], m0);
        __stcs(op + i * BLOCK, r);
    }
}

extern "C" void kernel_launch(void* const* d_in, const int* in_sizes, int n_in,
                              void* d_out, int out_size)
{
    const float4* coeff_cache = (const float4*)d_in[0];  // [65536,4] f32
    const int*    coeff_idx   = (const int*)d_in[1];     // [G] i32
    const int4*   bvr         = (const int4*)d_in[2];    // [G,4] i32
    float4*       out         = (float4*)d_out;          // [8192,8192] f32

    (void)in_sizes; (void)n_in; (void)out_size;

    sbvr_kernel<<<BLOCKS, BLOCK>>>(coeff_cache, coeff_idx, bvr, out);
}